// round 13
// baseline (speedup 1.0000x reference)
#include <cuda_runtime.h>
#include <math.h>

// Problem shape (fixed by the reference)
#define B 32
#define S 4096
#define H 768                 // 768 floats = 6 float4 per lane across a warp
#define WARPS 8
#define NROWS (B * S)         // 131072 global rows (hidden is contiguous)
#define RPC 443               // rows per CTA
#define GRID ((NROWS + RPC - 1) / RPC)   // 296 = exactly 2 CTAs per SM
#define MAXPART (GRID * 2)    // each CTA emits <= 2 partials (batch crossing)

// Scratch (allocation-free). g_count is statically zeroed and reset by each
// batch's combiner, so every graph replay starts from identical state.
__device__ float g_pm[MAXPART];
__device__ float g_pl[MAXPART];
__device__ float g_pacc[(size_t)MAXPART * H];   // ~1.8 MB, L2-resident
__device__ unsigned int g_count[B] = {};

// ---------------------------------------------------------------------------
// Fused single-query attention, perfectly balanced single wave:
//   - global flat row partition, 443 rows/CTA, 296 CTAs = 2/SM exactly
//   - CTAs straddling a batch boundary process 2 segments (flush each)
//   - register double-buffer with alternating consume (no x<-xn copies)
//   - q in smem; CTA smem merge; last-flusher-per-batch combine
// ---------------------------------------------------------------------------
__global__ __launch_bounds__(256, 2)
void attn_fused(const float* __restrict__ hidden, const float* __restrict__ q,
                float* __restrict__ out)
{
    const int bx   = blockIdx.x;             // 0..295
    const int wid  = threadIdx.x >> 5;
    const int lane = threadIdx.x & 31;

    __shared__ float s_q[H];                 // 3 KB
    __shared__ float s_m[WARPS];
    __shared__ float s_l[WARPS];
    __shared__ float s_acc[WARPS][H];        // 24 KB
    __shared__ unsigned int s_ticket;

    // stage q into smem (3 floats per thread)
#pragma unroll
    for (int j = 0; j < 3; j++)
        s_q[threadIdx.x + j * 256] = q[threadIdx.x + j * 256];
    __syncthreads();
    const float4* sq4 = (const float4*)s_q;

    const int g0 = bx * RPC;
    const int g1 = min(g0 + RPC, NROWS);
    const int b0 = g0 >> 12;                 // first batch touched
    const int b1 = (g1 - 1) >> 12;           // last batch touched (b0 or b0+1)

    #define LOADROW(buf, row) do {                                          \
        const float4* rp_ = (const float4*)(hidden + (size_t)(row) * H);    \
        _Pragma("unroll")                                                   \
        for (int i_ = 0; i_ < 6; i_++) buf[i_] = rp_[i_ * 32 + lane];       \
    } while (0)

    #define CONSUME(buf) do {                                               \
        float d0_ = 0.f, d1_ = 0.f;                                         \
        _Pragma("unroll")                                                   \
        for (int i_ = 0; i_ < 3; i_++) {                                    \
            const float4 qq_ = sq4[i_ * 32 + lane];                         \
            d0_ = fmaf(buf[i_].x, qq_.x, d0_);                              \
            d0_ = fmaf(buf[i_].y, qq_.y, d0_);                              \
            d0_ = fmaf(buf[i_].z, qq_.z, d0_);                              \
            d0_ = fmaf(buf[i_].w, qq_.w, d0_);                              \
        }                                                                   \
        _Pragma("unroll")                                                   \
        for (int i_ = 3; i_ < 6; i_++) {                                    \
            const float4 qq_ = sq4[i_ * 32 + lane];                         \
            d1_ = fmaf(buf[i_].x, qq_.x, d1_);                              \
            d1_ = fmaf(buf[i_].y, qq_.y, d1_);                              \
            d1_ = fmaf(buf[i_].z, qq_.z, d1_);                              \
            d1_ = fmaf(buf[i_].w, qq_.w, d1_);                              \
        }                                                                   \
        float d_ = d0_ + d1_;                                               \
        _Pragma("unroll")                                                   \
        for (int o_ = 16; o_ > 0; o_ >>= 1)                                 \
            d_ += __shfl_xor_sync(0xffffffffu, d_, o_);                     \
        if (d_ > m) {                                                       \
            const float sc_ = __expf(m - d_);                               \
            l *= sc_;                                                       \
            _Pragma("unroll")                                               \
            for (int i_ = 0; i_ < 6; i_++) {                                \
                acc[i_].x *= sc_; acc[i_].y *= sc_;                         \
                acc[i_].z *= sc_; acc[i_].w *= sc_;                         \
            }                                                               \
            m = d_;                                                         \
        }                                                                   \
        const float w_ = __expf(d_ - m);                                    \
        l += w_;                                                            \
        _Pragma("unroll")                                                   \
        for (int i_ = 0; i_ < 6; i_++) {                                    \
            acc[i_].x = fmaf(w_, buf[i_].x, acc[i_].x);                     \
            acc[i_].y = fmaf(w_, buf[i_].y, acc[i_].y);                     \
            acc[i_].z = fmaf(w_, buf[i_].z, acc[i_].z);                     \
            acc[i_].w = fmaf(w_, buf[i_].w, acc[i_].w);                     \
        }                                                                   \
    } while (0)

    for (int bb = b0; bb <= b1; bb++) {
        // this CTA's row segment inside batch bb, split across warps
        const int r0 = max(g0, bb << 12);
        const int r1 = min(g1, (bb + 1) << 12);
        const int len = r1 - r0;
        const int w0 = r0 + (wid * len) / WARPS;
        const int w1 = r0 + ((wid + 1) * len) / WARPS;
        const int nrows = w1 - w0;           // may be 0 for tiny segments

        float4 acc[6];
#pragma unroll
        for (int i = 0; i < 6; i++) acc[i] = make_float4(0.f, 0.f, 0.f, 0.f);
        float m = -INFINITY;
        float l = 0.f;

        float4 x[6], xn[6];
        if (nrows > 0) LOADROW(x, w0);

        // alternating double buffer: no register copies between rows
        int r = 0;
        while (r + 2 <= nrows) {
            LOADROW(xn, w0 + r + 1);
            CONSUME(x);
            if (r + 2 < nrows) LOADROW(x, w0 + r + 2);
            CONSUME(xn);
            r += 2;
        }
        if (r < nrows) CONSUME(x);           // odd leftover row (in x)

        // ---- CTA-level merge of the 8 warp partials through smem ----
        if (lane == 0) { s_m[wid] = m; s_l[wid] = l; }
        {
            float4* sa = (float4*)s_acc[wid];
#pragma unroll
            for (int i = 0; i < 6; i++) sa[i * 32 + lane] = acc[i];
        }
        __syncthreads();

        float M = s_m[0];
#pragma unroll
        for (int w = 1; w < WARPS; w++) M = fmaxf(M, s_m[w]);

        const int pidx = 2 * bx + (bb - b0);
        float* pa = g_pacc + (size_t)pidx * H;
#pragma unroll
        for (int j = 0; j < 3; j++) {
            const int h = threadIdx.x + j * 256;
            float rr = 0.f;
#pragma unroll
            for (int w = 0; w < WARPS; w++)
                rr = fmaf(__expf(s_m[w] - M), s_acc[w][h], rr);
            pa[h] = rr;
        }
        if (threadIdx.x == 0) {
            float L = 0.f;
#pragma unroll
            for (int w = 0; w < WARPS; w++)
                L = fmaf(__expf(s_m[w] - M), s_l[w], L);
            g_pm[pidx] = M;
            g_pl[pidx] = L;
        }

        // ---- ticket: last flusher for batch bb combines it ----
        const int cf = (bb << 12) / RPC;                         // first CTA
        const int cl = min((((bb + 1) << 12) - 1) / RPC, GRID - 1); // last CTA
        const unsigned cnt = (unsigned)(cl - cf + 1);

        __threadfence();                     // make THIS thread's stores visible
        __syncthreads();                     // all threads' fences complete
        if (threadIdx.x == 0) s_ticket = atomicAdd(&g_count[bb], 1u);
        __syncthreads();

        if (s_ticket == cnt - 1) {
            __threadfence();                 // acquire: see all partials

            float GM = -INFINITY;
            for (int c = cf; c <= cl; c++) {
                const int idx = 2 * c + (((c * RPC) >> 12) != bb ? 1 : 0);
                GM = fmaxf(GM, g_pm[idx]);
            }
            float rr0 = 0.f, rr1 = 0.f, rr2 = 0.f, L = 0.f;
            const int h0 = threadIdx.x;
            for (int c = cf; c <= cl; c++) {
                const int idx = 2 * c + (((c * RPC) >> 12) != bb ? 1 : 0);
                const float w = __expf(g_pm[idx] - GM);
                const float* pc = g_pacc + (size_t)idx * H;
                L   = fmaf(w, g_pl[idx], L);
                rr0 = fmaf(w, pc[h0],       rr0);
                rr1 = fmaf(w, pc[h0 + 256], rr1);
                rr2 = fmaf(w, pc[h0 + 512], rr2);
            }
            const float invL = 1.f / L;
            float* ob = out + bb * H;
            ob[h0]       = rr0 * invL;
            ob[h0 + 256] = rr1 * invL;
            ob[h0 + 512] = rr2 * invL;

            if (threadIdx.x == 0) g_count[bb] = 0;   // reset for next replay
        }
    }
}

extern "C" void kernel_launch(void* const* d_in, const int* in_sizes, int n_in,
                              void* d_out, int out_size)
{
    const float* hidden = (const float*)d_in[0];   // [32, 4096, 768] f32
    const float* querys = (const float*)d_in[1];   // [1, 768] f32
    float* out = (float*)d_out;                    // [32, 768] f32

    attn_fused<<<GRID, 256>>>(hidden, querys, out);
}

// round 15
// speedup vs baseline: 1.0350x; 1.0350x over previous
#include <cuda_runtime.h>
#include <math.h>

// Problem shape (fixed by the reference)
#define B 32
#define S 4096
#define H 768            // 768 floats = 6 float4 per lane across a warp
#define CHUNKS 9         // CTAs per batch -> 288 CTAs total (single wave)
#define WARPS 8          // warps per CTA
#define NPART (B * CHUNKS)                   // 288 CTA-level partials

// Scratch for CTA partials + per-batch arrival counters (allocation-free).
// g_count is statically zero-initialized; the last CTA of each batch resets
// its counter, so every graph replay starts from identical state.
__device__ float g_pm[NPART];
__device__ float g_pl[NPART];
__device__ float g_pacc[(size_t)NPART * H];   // 884 KB (L2-resident)
__device__ unsigned int g_count[B] = {};

// ---------------------------------------------------------------------------
// Fused single-query attention, single wave (R10 structure — best measured),
// with ONLY the inner loop changed: 2x-unrolled alternating double buffer
// (removes 24 x<-xn register MOVs per row; lets ptxas overlap dot(xn) with
// the butterfly+acc-update shadow of x).
// ---------------------------------------------------------------------------
__global__ __launch_bounds__(256, 2)
void attn_fused(const float* __restrict__ hidden, const float* __restrict__ q,
                float* __restrict__ out)
{
    const int bx    = blockIdx.x;            // 0..287
    const int b     = bx / CHUNKS;           // batch
    const int chunk = bx % CHUNKS;
    const int wid   = threadIdx.x >> 5;
    const int lane  = threadIdx.x & 31;

    const float4* qv4 = (const float4*)q;
    float4 qv[6];
#pragma unroll
    for (int i = 0; i < 6; i++) qv[i] = qv4[i * 32 + lane];

    const float* base = hidden + (size_t)b * S * H;

    // chunk row range within this batch, then warp sub-range (balanced splits)
    const int c0 = (chunk * S) / CHUNKS;
    const int c1 = ((chunk + 1) * S) / CHUNKS;
    const int w0 = c0 + (wid * (c1 - c0)) / WARPS;
    const int w1 = c0 + ((wid + 1) * (c1 - c0)) / WARPS;
    const int nrows = w1 - w0;               // ~56-57

    float4 acc[6];
#pragma unroll
    for (int i = 0; i < 6; i++) acc[i] = make_float4(0.f, 0.f, 0.f, 0.f);
    float m = -INFINITY;
    float l = 0.f;

    float4 x[6], xn[6];

    #define LOADROW(buf, row) do {                                          \
        const float4* rp_ = (const float4*)(base + (size_t)(row) * H);      \
        _Pragma("unroll")                                                   \
        for (int i_ = 0; i_ < 6; i_++) buf[i_] = rp_[i_ * 32 + lane];       \
    } while (0)

    #define CONSUME(buf) do {                                               \
        float d0_ = 0.f, d1_ = 0.f;                                         \
        _Pragma("unroll")                                                   \
        for (int i_ = 0; i_ < 3; i_++) {                                    \
            d0_ = fmaf(buf[i_].x, qv[i_].x, d0_);                           \
            d0_ = fmaf(buf[i_].y, qv[i_].y, d0_);                           \
            d0_ = fmaf(buf[i_].z, qv[i_].z, d0_);                           \
            d0_ = fmaf(buf[i_].w, qv[i_].w, d0_);                           \
        }                                                                   \
        _Pragma("unroll")                                                   \
        for (int i_ = 3; i_ < 6; i_++) {                                    \
            d1_ = fmaf(buf[i_].x, qv[i_].x, d1_);                           \
            d1_ = fmaf(buf[i_].y, qv[i_].y, d1_);                           \
            d1_ = fmaf(buf[i_].z, qv[i_].z, d1_);                           \
            d1_ = fmaf(buf[i_].w, qv[i_].w, d1_);                           \
        }                                                                   \
        float d_ = d0_ + d1_;                                               \
        _Pragma("unroll")                                                   \
        for (int o_ = 16; o_ > 0; o_ >>= 1)                                 \
            d_ += __shfl_xor_sync(0xffffffffu, d_, o_);                     \
        if (d_ > m) {                                                       \
            const float sc_ = __expf(m - d_);                               \
            l *= sc_;                                                       \
            _Pragma("unroll")                                               \
            for (int i_ = 0; i_ < 6; i_++) {                                \
                acc[i_].x *= sc_; acc[i_].y *= sc_;                         \
                acc[i_].z *= sc_; acc[i_].w *= sc_;                         \
            }                                                               \
            m = d_;                                                         \
        }                                                                   \
        const float w_ = __expf(d_ - m);                                    \
        l += w_;                                                            \
        _Pragma("unroll")                                                   \
        for (int i_ = 0; i_ < 6; i_++) {                                    \
            acc[i_].x = fmaf(w_, buf[i_].x, acc[i_].x);                     \
            acc[i_].y = fmaf(w_, buf[i_].y, acc[i_].y);                     \
            acc[i_].z = fmaf(w_, buf[i_].z, acc[i_].z);                     \
            acc[i_].w = fmaf(w_, buf[i_].w, acc[i_].w);                     \
        }                                                                   \
    } while (0)

    // prologue: first row resident
    LOADROW(x, w0);

    // 2x-unrolled alternating double buffer: no register copies between rows
    int r = 0;
    for (; r + 2 <= nrows; r += 2) {
        LOADROW(xn, w0 + r + 1);             // prefetch row r+1
        CONSUME(x);                          // consume row r
        if (r + 2 < nrows) LOADROW(x, w0 + r + 2);   // prefetch row r+2
        CONSUME(xn);                         // consume row r+1
    }
    if (r < nrows) CONSUME(x);               // odd leftover row

    // ---- CTA-level merge of the 8 warp partials through shared memory ----
    __shared__ float s_m[WARPS];
    __shared__ float s_l[WARPS];
    __shared__ float s_acc[WARPS][H];        // 24 KB
    __shared__ unsigned int s_ticket;

    if (lane == 0) { s_m[wid] = m; s_l[wid] = l; }
    {
        float4* sa = (float4*)s_acc[wid];
#pragma unroll
        for (int i = 0; i < 6; i++) sa[i * 32 + lane] = acc[i];
    }
    __syncthreads();

    float M = s_m[0];
#pragma unroll
    for (int w = 1; w < WARPS; w++) M = fmaxf(M, s_m[w]);

    // each thread owns 3 h-values: conflict-free LDS, coalesced STG
    float* pa = g_pacc + (size_t)bx * H;
#pragma unroll
    for (int j = 0; j < 3; j++) {
        const int h = threadIdx.x + j * 256;
        float rr = 0.f;
#pragma unroll
        for (int w = 0; w < WARPS; w++)
            rr = fmaf(__expf(s_m[w] - M), s_acc[w][h], rr);
        pa[h] = rr;
    }
    if (threadIdx.x == 0) {
        float L = 0.f;
#pragma unroll
        for (int w = 0; w < WARPS; w++) L = fmaf(__expf(s_m[w] - M), s_l[w], L);
        g_pm[bx] = M;
        g_pl[bx] = L;
    }

    // ---- last CTA of this batch combines the 9 partials ----
    if (threadIdx.x == 0) {
        __threadfence();                      // partials visible before count
        s_ticket = atomicAdd(&g_count[b], 1u);
    }
    __syncthreads();
    if (s_ticket != CHUNKS - 1) return;

    __threadfence();                          // acquire: see all partials

    const int p0 = b * CHUNKS;
    float GM = -INFINITY;
#pragma unroll
    for (int c = 0; c < CHUNKS; c++) GM = fmaxf(GM, g_pm[p0 + c]);

    float r0 = 0.f, r1 = 0.f, r2 = 0.f, L = 0.f;
    const int h0 = threadIdx.x;
#pragma unroll
    for (int c = 0; c < CHUNKS; c++) {
        const float w = __expf(g_pm[p0 + c] - GM);
        const float* pc = g_pacc + (size_t)(p0 + c) * H;
        L  = fmaf(w, g_pl[p0 + c], L);
        r0 = fmaf(w, pc[h0],       r0);
        r1 = fmaf(w, pc[h0 + 256], r1);
        r2 = fmaf(w, pc[h0 + 512], r2);
    }
    const float invL = 1.f / L;
    float* ob = out + b * H;
    ob[h0]       = r0 * invL;
    ob[h0 + 256] = r1 * invL;
    ob[h0 + 512] = r2 * invL;

    if (threadIdx.x == 0) g_count[b] = 0;     // reset for next graph replay
}

extern "C" void kernel_launch(void* const* d_in, const int* in_sizes, int n_in,
                              void* d_out, int out_size)
{
    const float* hidden = (const float*)d_in[0];   // [32, 4096, 768] f32
    const float* querys = (const float*)d_in[1];   // [1, 768] f32
    float* out = (float*)d_out;                    // [32, 768] f32

    attn_fused<<<B * CHUNKS, 256>>>(hidden, querys, out);
}

// round 16
// speedup vs baseline: 1.0745x; 1.0383x over previous
#include <cuda_runtime.h>
#include <math.h>

// Problem shape (fixed by the reference)
#define B 32
#define S 4096
#define H 768            // 768 floats = 6 float4 per lane across a warp
#define CHUNKS 9         // CTAs per batch -> 288 CTAs total (single wave)
#define WARPS 8          // warps per CTA
#define NPART (B * CHUNKS)                   // 288 CTA-level partials

// Scratch for CTA partials + per-batch arrival counters (allocation-free).
// g_count is statically zero-initialized; the last CTA of each batch resets
// its counter, so every graph replay starts from identical state.
__device__ float g_pm[NPART];
__device__ float g_pl[NPART];
__device__ float g_pacc[(size_t)NPART * H];   // 884 KB (L2-resident)
__device__ unsigned int g_count[B] = {};

// ---------------------------------------------------------------------------
// Fused single-query attention, single wave (R15 structure — best measured),
// with ONE change: the 8 warps of a CTA walk INTERLEAVED rows of the CTA's
// contiguous chunk (warp w -> rows w, w+8, w+16, ...). At any instant the
// CTA's in-flight loads cover one contiguous ~24-48 KB window instead of 8
// regions ~170 KB apart: ~288 effective DRAM streams instead of 2048, better
// HBM row-buffer + 2MB-page locality. Online softmax is order-invariant.
// ---------------------------------------------------------------------------
__global__ __launch_bounds__(256, 2)
void attn_fused(const float* __restrict__ hidden, const float* __restrict__ q,
                float* __restrict__ out)
{
    const int bx    = blockIdx.x;            // 0..287
    const int b     = bx / CHUNKS;           // batch
    const int chunk = bx % CHUNKS;
    const int wid   = threadIdx.x >> 5;
    const int lane  = threadIdx.x & 31;

    const float4* qv4 = (const float4*)q;
    float4 qv[6];
#pragma unroll
    for (int i = 0; i < 6; i++) qv[i] = qv4[i * 32 + lane];

    const float* base = hidden + (size_t)b * S * H;

    // CTA's contiguous chunk; warp takes every 8th row starting at wid
    const int c0  = (chunk * S) / CHUNKS;
    const int c1  = ((chunk + 1) * S) / CHUNKS;
    const int len = c1 - c0;                  // 455 or 456
    const int nrows = (len - wid + WARPS - 1) / WARPS;   // rows for this warp

    // per-warp row pointers, stride 8 rows = 8*H floats
    const float4* p = (const float4*)(base + (size_t)(c0 + wid) * H);
    const int STRIDE4 = (WARPS * H) / 4;      // float4 stride between my rows

    float4 acc[6];
#pragma unroll
    for (int i = 0; i < 6; i++) acc[i] = make_float4(0.f, 0.f, 0.f, 0.f);
    float m = -INFINITY;
    float l = 0.f;

    float4 x[6], xn[6];

    #define LOADROW(buf, k) do {                                            \
        const float4* rp_ = p + (size_t)(k) * STRIDE4;                      \
        _Pragma("unroll")                                                   \
        for (int i_ = 0; i_ < 6; i_++) buf[i_] = rp_[i_ * 32 + lane];       \
    } while (0)

    #define CONSUME(buf) do {                                               \
        float d0_ = 0.f, d1_ = 0.f;                                         \
        _Pragma("unroll")                                                   \
        for (int i_ = 0; i_ < 3; i_++) {                                    \
            d0_ = fmaf(buf[i_].x, qv[i_].x, d0_);                           \
            d0_ = fmaf(buf[i_].y, qv[i_].y, d0_);                           \
            d0_ = fmaf(buf[i_].z, qv[i_].z, d0_);                           \
            d0_ = fmaf(buf[i_].w, qv[i_].w, d0_);                           \
        }                                                                   \
        _Pragma("unroll")                                                   \
        for (int i_ = 3; i_ < 6; i_++) {                                    \
            d1_ = fmaf(buf[i_].x, qv[i_].x, d1_);                           \
            d1_ = fmaf(buf[i_].y, qv[i_].y, d1_);                           \
            d1_ = fmaf(buf[i_].z, qv[i_].z, d1_);                           \
            d1_ = fmaf(buf[i_].w, qv[i_].w, d1_);                           \
        }                                                                   \
        float d_ = d0_ + d1_;                                               \
        _Pragma("unroll")                                                   \
        for (int o_ = 16; o_ > 0; o_ >>= 1)                                 \
            d_ += __shfl_xor_sync(0xffffffffu, d_, o_);                     \
        if (d_ > m) {                                                       \
            const float sc_ = __expf(m - d_);                               \
            l *= sc_;                                                       \
            _Pragma("unroll")                                               \
            for (int i_ = 0; i_ < 6; i_++) {                                \
                acc[i_].x *= sc_; acc[i_].y *= sc_;                         \
                acc[i_].z *= sc_; acc[i_].w *= sc_;                         \
            }                                                               \
            m = d_;                                                         \
        }                                                                   \
        const float w_ = __expf(d_ - m);                                    \
        l += w_;                                                            \
        _Pragma("unroll")                                                   \
        for (int i_ = 0; i_ < 6; i_++) {                                    \
            acc[i_].x = fmaf(w_, buf[i_].x, acc[i_].x);                     \
            acc[i_].y = fmaf(w_, buf[i_].y, acc[i_].y);                     \
            acc[i_].z = fmaf(w_, buf[i_].z, acc[i_].z);                     \
            acc[i_].w = fmaf(w_, buf[i_].w, acc[i_].w);                     \
        }                                                                   \
    } while (0)

    // prologue: first row resident
    if (nrows > 0) LOADROW(x, 0);

    // 2x-unrolled alternating double buffer: no register copies between rows
    int r = 0;
    for (; r + 2 <= nrows; r += 2) {
        LOADROW(xn, r + 1);                   // prefetch my (r+1)-th row
        CONSUME(x);                           // consume my r-th row
        if (r + 2 < nrows) LOADROW(x, r + 2); // prefetch my (r+2)-th row
        CONSUME(xn);                          // consume my (r+1)-th row
    }
    if (r < nrows) CONSUME(x);                // odd leftover row

    // ---- CTA-level merge of the 8 warp partials through shared memory ----
    __shared__ float s_m[WARPS];
    __shared__ float s_l[WARPS];
    __shared__ float s_acc[WARPS][H];        // 24 KB
    __shared__ unsigned int s_ticket;

    if (lane == 0) { s_m[wid] = m; s_l[wid] = l; }
    {
        float4* sa = (float4*)s_acc[wid];
#pragma unroll
        for (int i = 0; i < 6; i++) sa[i * 32 + lane] = acc[i];
    }
    __syncthreads();

    float M = s_m[0];
#pragma unroll
    for (int w = 1; w < WARPS; w++) M = fmaxf(M, s_m[w]);

    // each thread owns 3 h-values: conflict-free LDS, coalesced STG
    float* pa = g_pacc + (size_t)bx * H;
#pragma unroll
    for (int j = 0; j < 3; j++) {
        const int h = threadIdx.x + j * 256;
        float rr = 0.f;
#pragma unroll
        for (int w = 0; w < WARPS; w++)
            rr = fmaf(__expf(s_m[w] - M), s_acc[w][h], rr);
        pa[h] = rr;
    }
    if (threadIdx.x == 0) {
        float L = 0.f;
#pragma unroll
        for (int w = 0; w < WARPS; w++) L = fmaf(__expf(s_m[w] - M), s_l[w], L);
        g_pm[bx] = M;
        g_pl[bx] = L;
    }

    // ---- last CTA of this batch combines the 9 partials ----
    if (threadIdx.x == 0) {
        __threadfence();                      // partials visible before count
        s_ticket = atomicAdd(&g_count[b], 1u);
    }
    __syncthreads();
    if (s_ticket != CHUNKS - 1) return;

    __threadfence();                          // acquire: see all partials

    const int p0 = b * CHUNKS;
    float GM = -INFINITY;
#pragma unroll
    for (int c = 0; c < CHUNKS; c++) GM = fmaxf(GM, g_pm[p0 + c]);

    float r0 = 0.f, r1 = 0.f, r2 = 0.f, L = 0.f;
    const int h0 = threadIdx.x;
#pragma unroll
    for (int c = 0; c < CHUNKS; c++) {
        const float w = __expf(g_pm[p0 + c] - GM);
        const float* pc = g_pacc + (size_t)(p0 + c) * H;
        L  = fmaf(w, g_pl[p0 + c], L);
        r0 = fmaf(w, pc[h0],       r0);
        r1 = fmaf(w, pc[h0 + 256], r1);
        r2 = fmaf(w, pc[h0 + 512], r2);
    }
    const float invL = 1.f / L;
    float* ob = out + b * H;
    ob[h0]       = r0 * invL;
    ob[h0 + 256] = r1 * invL;
    ob[h0 + 512] = r2 * invL;

    if (threadIdx.x == 0) g_count[b] = 0;     // reset for next graph replay
}

extern "C" void kernel_launch(void* const* d_in, const int* in_sizes, int n_in,
                              void* d_out, int out_size)
{
    const float* hidden = (const float*)d_in[0];   // [32, 4096, 768] f32
    const float* querys = (const float*)d_in[1];   // [1, 768] f32
    float* out = (float*)d_out;                    // [32, 768] f32

    attn_fused<<<B * CHUNKS, 256>>>(hidden, querys, out);
}